// round 5
// baseline (speedup 1.0000x reference)
#include <cuda_runtime.h>
#include <cstdint>

// Problem constants
#define BB   32
#define KK_  3
#define NN   512
#define FIN  64
#define FOUT 64
#define TT   64
// Derived
#define KC   (KK_ * NN)          // 1536 contraction depth
#define CC   (FOUT * TT)         // 4096 output cols per row

// Scratch (allocation-free rule: __device__ globals)
__device__ float g_aeff[(size_t)BB * NN * KC];          // [b][n][k*512+m]  ~100.7 MB
__device__ float g_xt  [(size_t)BB * KC * CC];          // [b][k*512+m][o*64+t] ~805 MB

typedef unsigned long long u64;

__device__ __forceinline__ u64 pk2(float x, float y) {
    u64 r; asm("mov.b64 %0, {%1, %2};" : "=l"(r) : "f"(x), "f"(y)); return r;
}
__device__ __forceinline__ void fma2(u64 &c, u64 a, u64 b) {
    asm("fma.rn.f32x2 %0, %1, %2, %0;" : "+l"(c) : "l"(a), "l"(b));
}
__device__ __forceinline__ void unpk2(u64 v, float &x, float &y) {
    asm("mov.b64 {%0, %1}, %2;" : "=f"(x), "=f"(y) : "l"(v));
}

// ---------------------------------------------------------------------------
// K1: combined = scores + adj*mask; softmax over last axis; A_eff = cheb * sm
// Writes A_eff transposed to [b][n][k*512+m] so K3 sees a plain [512,1536] A.
// grid (N, K, B), block 128; each thread owns one float4 (4 of 512 elems).
// ---------------------------------------------------------------------------
__global__ __launch_bounds__(128)
void k_aeff(const float* __restrict__ sc, const float* __restrict__ adj,
            const float* __restrict__ mask, const float* __restrict__ cheb)
{
    int n = blockIdx.x, k = blockIdx.y, b = blockIdx.z;
    const float4* s4 = (const float4*)(sc   + (((size_t)(b * KK_ + k)) * NN + n) * NN);
    const float4* a4 = (const float4*)(adj  + (size_t)n * NN);
    const float4* m4 = (const float4*)(mask + ((size_t)(k * NN + n)) * NN);
    const float4* c4 = (const float4*)(cheb + ((size_t)(k * NN + n)) * NN);
    float4*       o4 = (float4*)(g_aeff + ((size_t)(b * NN + n)) * KC + k * NN);

    int t = threadIdx.x;
    float4 sv = s4[t], av = a4[t], mv = m4[t];
    float v0 = sv.x + av.x * mv.x;
    float v1 = sv.y + av.y * mv.y;
    float v2 = sv.z + av.z * mv.z;
    float v3 = sv.w + av.w * mv.w;

    float mx = fmaxf(fmaxf(v0, v1), fmaxf(v2, v3));
    __shared__ float red[4];
    #pragma unroll
    for (int o = 16; o; o >>= 1) mx = fmaxf(mx, __shfl_xor_sync(0xffffffffu, mx, o));
    if ((t & 31) == 0) red[t >> 5] = mx;
    __syncthreads();
    mx = fmaxf(fmaxf(red[0], red[1]), fmaxf(red[2], red[3]));
    __syncthreads();

    v0 = __expf(v0 - mx); v1 = __expf(v1 - mx);
    v2 = __expf(v2 - mx); v3 = __expf(v3 - mx);
    float s = v0 + v1 + v2 + v3;
    #pragma unroll
    for (int o = 16; o; o >>= 1) s += __shfl_xor_sync(0xffffffffu, s, o);
    if ((t & 31) == 0) red[t >> 5] = s;
    __syncthreads();
    s = red[0] + red[1] + red[2] + red[3];
    float inv = 1.0f / s;

    float4 cv = c4[t];
    float4 ov;
    ov.x = cv.x * v0 * inv; ov.y = cv.y * v1 * inv;
    ov.z = cv.z * v2 * inv; ov.w = cv.w * v3 * inv;
    o4[t] = ov;
}

// ---------------------------------------------------------------------------
// K2: XT[b,k,m,o,t] = sum_i x[b,m,i,t] * Theta[k,i,o]
// grid (N, B), block 256. Per CTA: X = x[b,m] (64x64) in smem, loop k over 3
// Theta matrices. 4x4 micro per thread, packed f32x2 FMAs.
// ---------------------------------------------------------------------------
__global__ __launch_bounds__(256)
void k_xtheta(const float* __restrict__ x, const float* __restrict__ Theta)
{
    int m = blockIdx.x, b = blockIdx.y;
    __shared__ float Xs[FIN * TT];   // [i][t]
    __shared__ float Ts[FIN * FOUT]; // [i][o]

    int tid = threadIdx.x;
    const float4* xb4 = (const float4*)(x + ((size_t)(b * NN + m)) * (FIN * TT));
    float4* Xs4 = (float4*)Xs;
    #pragma unroll
    for (int r = 0; r < 4; r++) Xs4[tid + r * 256] = xb4[tid + r * 256];

    int tx = tid & 15;   // t-quad
    int ty = tid >> 4;   // o-quad

    for (int k = 0; k < KK_; k++) {
        __syncthreads();  // Xs ready (k=0) / previous compute done (k>0)
        const float4* th4 = (const float4*)(Theta + (size_t)k * FIN * FOUT);
        float4* Ts4 = (float4*)Ts;
        #pragma unroll
        for (int r = 0; r < 4; r++) Ts4[tid + r * 256] = th4[tid + r * 256];
        __syncthreads();

        u64 acc[4][2] = {};
        #pragma unroll 8
        for (int i = 0; i < FIN; i++) {
            float4 th = ((const float4*)(Ts + i * FOUT))[ty];
            float4 xv = ((const float4*)(Xs + i * TT))[tx];
            u64 b01 = pk2(xv.x, xv.y), b23 = pk2(xv.z, xv.w);
            u64 a0 = pk2(th.x, th.x), a1 = pk2(th.y, th.y);
            u64 a2 = pk2(th.z, th.z), a3 = pk2(th.w, th.w);
            fma2(acc[0][0], a0, b01); fma2(acc[0][1], a0, b23);
            fma2(acc[1][0], a1, b01); fma2(acc[1][1], a1, b23);
            fma2(acc[2][0], a2, b01); fma2(acc[2][1], a2, b23);
            fma2(acc[3][0], a3, b01); fma2(acc[3][1], a3, b23);
        }

        float* orow = g_xt + ((size_t)((b * KK_ + k) * NN + m)) * CC;
        #pragma unroll
        for (int oi = 0; oi < 4; oi++) {
            float4 v;
            unpk2(acc[oi][0], v.x, v.y);
            unpk2(acc[oi][1], v.z, v.w);
            *(float4*)(orow + (size_t)(ty * 4 + oi) * TT + tx * 4) = v;
        }
    }
}

// ---------------------------------------------------------------------------
// K3: per-b GEMM + ReLU: out[b] (512x4096) = A_eff[b] (512x1536) @ XT[b] (1536x4096)
// CTA tile 128x64, BK=32, 256 threads, 8x4 micro per thread, f32x2 FMAs.
// grid (4096/64, 512/128, B) = (64, 4, 32).
// ---------------------------------------------------------------------------
__global__ __launch_bounds__(256)
void k_gemm_relu(float* __restrict__ Cg)
{
    const int BM = 128, BN = 64, BK = 32;
    int ct = blockIdx.x, nt = blockIdx.y, b = blockIdx.z;

    const float* A  = g_aeff + ((size_t)b * NN + nt * BM) * KC;
    const float* Bm = g_xt   + (size_t)b * KC * CC + ct * BN;
    float*       C  = Cg     + ((size_t)b * NN + nt * BM) * CC + ct * BN;

    __shared__ float As[BM * BK];   // [row][kk], 16 KB
    __shared__ float Bs[BK * BN];   // [kk][c],   8 KB

    int tid = threadIdx.x;
    int tx = tid & 15;   // c-quad
    int ty = tid >> 4;   // n-octet

    u64 acc[8][2] = {};

    for (int kt = 0; kt < KC / BK; kt++) {
        __syncthreads();
        // A tile: 128 rows x 32 cols = 1024 float4, 4 per thread (coalesced)
        #pragma unroll
        for (int r = 0; r < 4; r++) {
            int lin = tid + r * 256;
            int row = lin >> 3, q = lin & 7;
            float4 v = *(const float4*)(A + (size_t)row * KC + kt * BK + q * 4);
            *(float4*)(As + row * BK + q * 4) = v;
        }
        // B tile: 32 rows x 64 cols = 512 float4, 2 per thread (coalesced)
        #pragma unroll
        for (int r = 0; r < 2; r++) {
            int lin = tid + r * 256;
            int row = lin >> 4, q = lin & 15;
            float4 v = *(const float4*)(Bm + (size_t)(kt * BK + row) * CC + q * 4);
            *(float4*)(Bs + row * BN + q * 4) = v;
        }
        __syncthreads();

        #pragma unroll 8
        for (int kk = 0; kk < BK; kk++) {
            float4 bv = ((const float4*)(Bs + kk * BN))[tx];
            u64 b01 = pk2(bv.x, bv.y), b23 = pk2(bv.z, bv.w);
            #pragma unroll
            for (int i = 0; i < 8; i++) {
                float a = As[(ty * 8 + i) * BK + kk];  // broadcast LDS
                u64 a2 = pk2(a, a);
                fma2(acc[i][0], a2, b01);
                fma2(acc[i][1], a2, b23);
            }
        }
    }

    #pragma unroll
    for (int i = 0; i < 8; i++) {
        float o0, o1, o2, o3;
        unpk2(acc[i][0], o0, o1);
        unpk2(acc[i][1], o2, o3);
        float4 v = make_float4(fmaxf(o0, 0.f), fmaxf(o1, 0.f),
                               fmaxf(o2, 0.f), fmaxf(o3, 0.f));
        *(float4*)(C + (size_t)(ty * 8 + i) * CC + tx * 4) = v;
    }
}

// ---------------------------------------------------------------------------
extern "C" void kernel_launch(void* const* d_in, const int* in_sizes, int n_in,
                              void* d_out, int out_size)
{
    const float* x     = (const float*)d_in[0];  // [B,N,F_IN,T]
    const float* sc    = (const float*)d_in[1];  // [B,K,N,N]
    const float* adj   = (const float*)d_in[2];  // [N,N]
    const float* cheb  = (const float*)d_in[3];  // [K,N,N]
    const float* Theta = (const float*)d_in[4];  // [K,F_IN,F_OUT]
    const float* mask  = (const float*)d_in[5];  // [K,N,N]
    float* out = (float*)d_out;                  // [B,N,F_OUT,T]
    (void)in_sizes; (void)n_in; (void)out_size;

    k_aeff<<<dim3(NN, KK_, BB), 128>>>(sc, adj, mask, cheb);
    k_xtheta<<<dim3(NN, BB), 256>>>(x, Theta);
    k_gemm_relu<<<dim3(CC / 64, NN / 128, BB), 256>>>(out);
}

// round 9
// speedup vs baseline: 2.4513x; 2.4513x over previous
#include <cuda_runtime.h>
#include <cstdint>

#define BB   32
#define KK_  3
#define NN   512
#define FIN  64
#define FOUT 64
#define TT   64
#define KC   (KK_ * NN)
#define CC   (FOUT * TT)

__device__ float g_aeff[(size_t)BB * NN * KC];
__device__ float g_xt  [(size_t)BB * KC * CC];
__device__ float g_xtT [(size_t)BB * CC * KC];

typedef unsigned long long u64;

__device__ __forceinline__ u64 pk2(float x, float y) {
    u64 r; asm("mov.b64 %0, {%1, %2};" : "=l"(r) : "f"(x), "f"(y)); return r;
}
__device__ __forceinline__ void fma2(u64 &c, u64 a, u64 b) {
    asm("fma.rn.f32x2 %0, %1, %2, %0;" : "+l"(c) : "l"(a), "l"(b));
}
__device__ __forceinline__ void unpk2(u64 v, float &x, float &y) {
    asm("mov.b64 {%0, %1}, %2;" : "=f"(x), "=f"(y) : "l"(v));
}
__device__ __forceinline__ float tf32r(float x) {
    float r; asm("cvt.rna.tf32.f32 %0, %1;" : "=f"(r) : "f"(x)); return r;
}
__device__ __forceinline__ uint32_t smem_u32(const void* p) {
    uint32_t a;
    asm("{ .reg .u64 t; cvta.to.shared.u64 t, %1; cvt.u32.u64 %0, t; }" : "=r"(a) : "l"(p));
    return a;
}
__device__ __forceinline__ void cp16(uint32_t dst, const void* src) {
    asm volatile("cp.async.cg.shared.global [%0], [%1], 16;" :: "r"(dst), "l"(src));
}
__device__ __forceinline__ uint32_t lds32(uint32_t a) {
    uint32_t v; asm("ld.shared.b32 %0, [%1];" : "=r"(v) : "r"(a)); return v;
}
__device__ __forceinline__ void mma_tf32(float* c, const uint32_t* a, const uint32_t* b) {
    asm("mma.sync.aligned.m16n8k8.row.col.f32.tf32.tf32.f32 "
        "{%0,%1,%2,%3}, {%4,%5,%6,%7}, {%8,%9}, {%0,%1,%2,%3};"
        : "+f"(c[0]), "+f"(c[1]), "+f"(c[2]), "+f"(c[3])
        : "r"(a[0]), "r"(a[1]), "r"(a[2]), "r"(a[3]), "r"(b[0]), "r"(b[1]));
}
#define CP_COMMIT() asm volatile("cp.async.commit_group;" ::: "memory")
#define CP_WAIT1()  asm volatile("cp.async.wait_group 1;" ::: "memory")
#define SWZ(bo) ((bo) ^ (((bo) >> 3) & 0x70))

__global__ __launch_bounds__(128)
void k_aeff(const float* __restrict__ sc, const float* __restrict__ adj,
            const float* __restrict__ mask, const float* __restrict__ cheb)
{
    int n = blockIdx.x, k = blockIdx.y, b = blockIdx.z;
    const float4* s4 = (const float4*)(sc   + (((size_t)(b * KK_ + k)) * NN + n) * NN);
    const float4* a4 = (const float4*)(adj  + (size_t)n * NN);
    const float4* m4 = (const float4*)(mask + ((size_t)(k * NN + n)) * NN);
    const float4* c4 = (const float4*)(cheb + ((size_t)(k * NN + n)) * NN);
    float4*       o4 = (float4*)(g_aeff + ((size_t)(b * NN + n)) * KC + k * NN);

    int t = threadIdx.x;
    float4 sv = s4[t], av = a4[t], mv = m4[t];
    float v0 = sv.x + av.x * mv.x;
    float v1 = sv.y + av.y * mv.y;
    float v2 = sv.z + av.z * mv.z;
    float v3 = sv.w + av.w * mv.w;

    float mx = fmaxf(fmaxf(v0, v1), fmaxf(v2, v3));
    __shared__ float red[4];
    #pragma unroll
    for (int o = 16; o; o >>= 1) mx = fmaxf(mx, __shfl_xor_sync(0xffffffffu, mx, o));
    if ((t & 31) == 0) red[t >> 5] = mx;
    __syncthreads();
    mx = fmaxf(fmaxf(red[0], red[1]), fmaxf(red[2], red[3]));
    __syncthreads();

    v0 = __expf(v0 - mx); v1 = __expf(v1 - mx);
    v2 = __expf(v2 - mx); v3 = __expf(v3 - mx);
    float s = v0 + v1 + v2 + v3;
    #pragma unroll
    for (int o = 16; o; o >>= 1) s += __shfl_xor_sync(0xffffffffu, s, o);
    if ((t & 31) == 0) red[t >> 5] = s;
    __syncthreads();
    s = red[0] + red[1] + red[2] + red[3];
    float inv = 1.0f / s;

    float4 cv = c4[t];
    float4 ov;
    ov.x = tf32r(cv.x * v0 * inv); ov.y = tf32r(cv.y * v1 * inv);
    ov.z = tf32r(cv.z * v2 * inv); ov.w = tf32r(cv.w * v3 * inv);
    o4[t] = ov;
}

__global__ __launch_bounds__(256)
void k_xtheta(const float* __restrict__ x, const float* __restrict__ Theta)
{
    int m = blockIdx.x, b = blockIdx.y;
    __shared__ float Xs[FIN * TT];
    __shared__ float Ts[FIN * FOUT];

    int tid = threadIdx.x;
    const float4* xb4 = (const float4*)(x + ((size_t)(b * NN + m)) * (FIN * TT));
    float4* Xs4 = (float4*)Xs;
    #pragma unroll
    for (int r = 0; r < 4; r++) Xs4[tid + r * 256] = xb4[tid + r * 256];

    int tx = tid & 15;
    int ty = tid >> 4;

    for (int k = 0; k < KK_; k++) {
        __syncthreads();
        const float4* th4 = (const float4*)(Theta + (size_t)k * FIN * FOUT);
        float4* Ts4 = (float4*)Ts;
        #pragma unroll
        for (int r = 0; r < 4; r++) Ts4[tid + r * 256] = th4[tid + r * 256];
        __syncthreads();

        u64 acc[4][2] = {};
        #pragma unroll 8
        for (int i = 0; i < FIN; i++) {
            float4 th = ((const float4*)(Ts + i * FOUT))[ty];
            float4 xv = ((const float4*)(Xs + i * TT))[tx];
            u64 b01 = pk2(xv.x, xv.y), b23 = pk2(xv.z, xv.w);
            u64 a0 = pk2(th.x, th.x), a1 = pk2(th.y, th.y);
            u64 a2 = pk2(th.z, th.z), a3 = pk2(th.w, th.w);
            fma2(acc[0][0], a0, b01); fma2(acc[0][1], a0, b23);
            fma2(acc[1][0], a1, b01); fma2(acc[1][1], a1, b23);
            fma2(acc[2][0], a2, b01); fma2(acc[2][1], a2, b23);
            fma2(acc[3][0], a3, b01); fma2(acc[3][1], a3, b23);
        }

        float* orow = g_xt + ((size_t)((b * KK_ + k) * NN + m)) * CC;
        #pragma unroll
        for (int oi = 0; oi < 4; oi++) {
            float4 v;
            unpk2(acc[oi][0], v.x, v.y);
            unpk2(acc[oi][1], v.z, v.w);
            v.x = tf32r(v.x); v.y = tf32r(v.y); v.z = tf32r(v.z); v.w = tf32r(v.w);
            *(float4*)(orow + (size_t)(ty * 4 + oi) * TT + tx * 4) = v;
        }
    }
}

__global__ __launch_bounds__(256)
void k_xt_transpose()
{
    __shared__ float tile[32][33];
    int c0 = blockIdx.x * 32, kc0 = blockIdx.y * 32, b = blockIdx.z;
    int tx = threadIdx.x & 31, ty = threadIdx.x >> 5;
    const float* src = g_xt + (size_t)b * KC * CC;
    float* dst = g_xtT + (size_t)b * CC * KC;
    #pragma unroll
    for (int k = 0; k < 4; k++) {
        int r = ty + k * 8;
        tile[r][tx] = src[(size_t)(kc0 + r) * CC + c0 + tx];
    }
    __syncthreads();
    #pragma unroll
    for (int k = 0; k < 4; k++) {
        int r = ty + k * 8;
        dst[(size_t)(c0 + r) * KC + kc0 + tx] = tile[tx][r];
    }
}

#define ST_BYTES 49152
#define SMEM_GEMM (3 * ST_BYTES + 1024)

__global__ __launch_bounds__(512, 1)
void k_gemm_tc(float* __restrict__ Cg)
{
    extern __shared__ char dsm[];
    uint32_t base = (smem_u32(dsm) + 1023) & ~1023u;

    int tid  = threadIdx.x;
    int lane = tid & 31, wid = tid >> 5;
    int wm = wid & 3, wn = wid >> 2;
    int g = lane >> 2, tig = lane & 3;
    uint32_t xorv = (uint32_t)g << 4;

    int b = blockIdx.z, nt = blockIdx.y, ct = blockIdx.x;
    const float* Abase = g_aeff + ((size_t)(b * NN) + nt * 128) * KC;
    const float* Bbase = g_xtT  + ((size_t)b * CC + ct * 256) * KC;

    const int NCHUNK = KC / 32;

    float acc[2][8][4] = {};

    #define ISSUE(kt, s) do {                                                   \
        uint32_t stA = base + (s) * ST_BYTES, stB = stA + 16384;                \
        int koff = (kt) * 32;                                                   \
        _Pragma("unroll")                                                       \
        for (int r = 0; r < 2; r++) {                                           \
            int idx = tid + r * 512;                                            \
            int row = idx >> 3, p = idx & 7;                                    \
            cp16(stA + SWZ((uint32_t)(row * 128 + p * 16)),                     \
                 Abase + (size_t)row * KC + koff + p * 4);                      \
        }                                                                       \
        _Pragma("unroll")                                                       \
        for (int r = 0; r < 4; r++) {                                           \
            int idx = tid + r * 512;                                            \
            int c = idx >> 3, p = idx & 7;                                      \
            cp16(stB + SWZ((uint32_t)(c * 128 + p * 16)),                       \
                 Bbase + (size_t)c * KC + koff + p * 4);                        \
        }                                                                       \
    } while (0)

    ISSUE(0, 0); CP_COMMIT();
    ISSUE(1, 1); CP_COMMIT();

    for (int kt = 0; kt < NCHUNK; kt++) {
        CP_WAIT1();
        __syncthreads();
        int s = kt % 3;
        uint32_t stA = base + s * ST_BYTES, stB = stA + 16384;

        #pragma unroll
        for (int ks = 0; ks < 4; ks++) {
            uint32_t col0 = ((uint32_t)(ks * 8 + tig) * 4) ^ xorv;
            uint32_t col1 = ((uint32_t)(ks * 8 + tig + 4) * 4) ^ xorv;
            uint32_t a[2][4], bb[8][2];
            #pragma unroll
            for (int i = 0; i < 2; i++) {
                uint32_t r0 = (uint32_t)(wm * 32 + i * 16 + g) * 128;
                a[i][0] = lds32(stA + r0 + col0);
                a[i][1] = lds32(stA + r0 + 1024 + col0);
                a[i][2] = lds32(stA + r0 + col1);
                a[i][3] = lds32(stA + r0 + 1024 + col1);
            }
            #pragma unroll
            for (int j = 0; j < 8; j++) {
                uint32_t n0 = (uint32_t)(wn * 64 + j * 8 + g) * 128;
                bb[j][0] = lds32(stB + n0 + col0);
                bb[j][1] = lds32(stB + n0 + col1);
            }
            #pragma unroll
            for (int i = 0; i < 2; i++)
                #pragma unroll
                for (int j = 0; j < 8; j++)
                    mma_tf32(acc[i][j], a[i], bb[j]);
        }

        if (kt + 2 < NCHUNK) ISSUE(kt + 2, (kt + 2) % 3);
        CP_COMMIT();
    }

    float* C = Cg + ((size_t)(b * NN) + nt * 128) * CC + ct * 256;
    #pragma unroll
    for (int i = 0; i < 2; i++) {
        int row0 = wm * 32 + i * 16 + g;
        #pragma unroll
        for (int j = 0; j < 8; j++) {
            int col = wn * 64 + j * 8 + tig * 2;
            float2 v0 = make_float2(fmaxf(acc[i][j][0], 0.f), fmaxf(acc[i][j][1], 0.f));
            float2 v1 = make_float2(fmaxf(acc[i][j][2], 0.f), fmaxf(acc[i][j][3], 0.f));
            *(float2*)(C + (size_t)row0 * CC + col) = v0;
            *(float2*)(C + (size_t)(row0 + 8) * CC + col) = v1;
        }
    }
    #undef ISSUE
}

extern "C" void kernel_launch(void* const* d_in, const int* in_sizes, int n_in,
                              void* d_out, int out_size)
{
    const float* x     = (const float*)d_in[0];
    const float* sc    = (const float*)d_in[1];
    const float* adj   = (const float*)d_in[2];
    const float* cheb  = (const float*)d_in[3];
    const float* Theta = (const float*)d_in[4];
    const float* mask  = (const float*)d_in[5];
    float* out = (float*)d_out;
    (void)in_sizes; (void)n_in; (void)out_size;

    cudaFuncSetAttribute(k_gemm_tc, cudaFuncAttributeMaxDynamicSharedMemorySize, SMEM_GEMM);

    k_aeff<<<dim3(NN, KK_, BB), 128>>>(sc, adj, mask, cheb);
    k_xtheta<<<dim3(NN, BB), 256>>>(x, Theta);
    k_xt_transpose<<<dim3(CC / 32, KC / 32, BB), 256>>>();
    k_gemm_tc<<<dim3(CC / 256, NN / 128, BB), 512, SMEM_GEMM>>>(out);
}

// round 10
// speedup vs baseline: 2.8228x; 1.1515x over previous
#include <cuda_runtime.h>
#include <cstdint>

#define BB   32
#define KK_  3
#define NN   512
#define FIN  64
#define FOUT 64
#define TT   64
#define KC   (KK_ * NN)          // 1536
#define CC   (FOUT * TT)         // 4096

__device__ float g_aeff[(size_t)BB * NN * KC];   // [b][n][k*512+m]  (tf32-rounded)
__device__ float g_xt  [(size_t)BB * KC * CC];   // [b][kc][c]       (tf32-rounded)

typedef unsigned long long u64;

__device__ __forceinline__ u64 pk2(float x, float y) {
    u64 r; asm("mov.b64 %0, {%1, %2};" : "=l"(r) : "f"(x), "f"(y)); return r;
}
__device__ __forceinline__ void fma2(u64 &c, u64 a, u64 b) {
    asm("fma.rn.f32x2 %0, %1, %2, %0;" : "+l"(c) : "l"(a), "l"(b));
}
__device__ __forceinline__ void unpk2(u64 v, float &x, float &y) {
    asm("mov.b64 {%0, %1}, %2;" : "=f"(x), "=f"(y) : "l"(v));
}
__device__ __forceinline__ float tf32r(float x) {
    float r; asm("cvt.rna.tf32.f32 %0, %1;" : "=f"(r) : "f"(x)); return r;
}
__device__ __forceinline__ uint32_t smem_u32(const void* p) {
    uint32_t a;
    asm("{ .reg .u64 t; cvta.to.shared.u64 t, %1; cvt.u32.u64 %0, t; }" : "=r"(a) : "l"(p));
    return a;
}
__device__ __forceinline__ void cp16(uint32_t dst, const void* src) {
    asm volatile("cp.async.cg.shared.global [%0], [%1], 16;" :: "r"(dst), "l"(src));
}
__device__ __forceinline__ uint32_t lds32(uint32_t a) {
    uint32_t v; asm("ld.shared.b32 %0, [%1];" : "=r"(v) : "r"(a)); return v;
}
__device__ __forceinline__ void mma_tf32(float* c, const uint32_t* a, const uint32_t* b) {
    asm("mma.sync.aligned.m16n8k8.row.col.f32.tf32.tf32.f32 "
        "{%0,%1,%2,%3}, {%4,%5,%6,%7}, {%8,%9}, {%0,%1,%2,%3};"
        : "+f"(c[0]), "+f"(c[1]), "+f"(c[2]), "+f"(c[3])
        : "r"(a[0]), "r"(a[1]), "r"(a[2]), "r"(a[3]), "r"(b[0]), "r"(b[1]));
}
#define CP_COMMIT() asm volatile("cp.async.commit_group;" ::: "memory")
#define CP_WAIT2()  asm volatile("cp.async.wait_group 2;" ::: "memory")
#define SWZ(bo) ((bo) ^ (((bo) >> 3) & 0x70))

// ---------------------------------------------------------------------------
// K1: softmax + A_eff, written [b][n][k*512+m], tf32-rounded
// ---------------------------------------------------------------------------
__global__ __launch_bounds__(128)
void k_aeff(const float* __restrict__ sc, const float* __restrict__ adj,
            const float* __restrict__ mask, const float* __restrict__ cheb)
{
    int n = blockIdx.x, k = blockIdx.y, b = blockIdx.z;
    const float4* s4 = (const float4*)(sc   + (((size_t)(b * KK_ + k)) * NN + n) * NN);
    const float4* a4 = (const float4*)(adj  + (size_t)n * NN);
    const float4* m4 = (const float4*)(mask + ((size_t)(k * NN + n)) * NN);
    const float4* c4 = (const float4*)(cheb + ((size_t)(k * NN + n)) * NN);
    float4*       o4 = (float4*)(g_aeff + ((size_t)(b * NN + n)) * KC + k * NN);

    int t = threadIdx.x;
    float4 sv = s4[t], av = a4[t], mv = m4[t];
    float v0 = sv.x + av.x * mv.x;
    float v1 = sv.y + av.y * mv.y;
    float v2 = sv.z + av.z * mv.z;
    float v3 = sv.w + av.w * mv.w;

    float mx = fmaxf(fmaxf(v0, v1), fmaxf(v2, v3));
    __shared__ float red[4];
    #pragma unroll
    for (int o = 16; o; o >>= 1) mx = fmaxf(mx, __shfl_xor_sync(0xffffffffu, mx, o));
    if ((t & 31) == 0) red[t >> 5] = mx;
    __syncthreads();
    mx = fmaxf(fmaxf(red[0], red[1]), fmaxf(red[2], red[3]));
    __syncthreads();

    v0 = __expf(v0 - mx); v1 = __expf(v1 - mx);
    v2 = __expf(v2 - mx); v3 = __expf(v3 - mx);
    float s = v0 + v1 + v2 + v3;
    #pragma unroll
    for (int o = 16; o; o >>= 1) s += __shfl_xor_sync(0xffffffffu, s, o);
    if ((t & 31) == 0) red[t >> 5] = s;
    __syncthreads();
    s = red[0] + red[1] + red[2] + red[3];
    float inv = 1.0f / s;

    float4 cv = c4[t];
    float4 ov;
    ov.x = tf32r(cv.x * v0 * inv); ov.y = tf32r(cv.y * v1 * inv);
    ov.z = tf32r(cv.z * v2 * inv); ov.w = tf32r(cv.w * v3 * inv);
    o4[t] = ov;
}

// ---------------------------------------------------------------------------
// K2: XT[b,k,m,c] = sum_i x[b,m,i,t] * Theta[k,i,o], tf32-rounded
// ---------------------------------------------------------------------------
__global__ __launch_bounds__(256)
void k_xtheta(const float* __restrict__ x, const float* __restrict__ Theta)
{
    int m = blockIdx.x, b = blockIdx.y;
    __shared__ float Xs[FIN * TT];
    __shared__ float Ts[FIN * FOUT];

    int tid = threadIdx.x;
    const float4* xb4 = (const float4*)(x + ((size_t)(b * NN + m)) * (FIN * TT));
    float4* Xs4 = (float4*)Xs;
    #pragma unroll
    for (int r = 0; r < 4; r++) Xs4[tid + r * 256] = xb4[tid + r * 256];

    int tx = tid & 15;
    int ty = tid >> 4;

    for (int k = 0; k < KK_; k++) {
        __syncthreads();
        const float4* th4 = (const float4*)(Theta + (size_t)k * FIN * FOUT);
        float4* Ts4 = (float4*)Ts;
        #pragma unroll
        for (int r = 0; r < 4; r++) Ts4[tid + r * 256] = th4[tid + r * 256];
        __syncthreads();

        u64 acc[4][2] = {};
        #pragma unroll 8
        for (int i = 0; i < FIN; i++) {
            float4 th = ((const float4*)(Ts + i * FOUT))[ty];
            float4 xv = ((const float4*)(Xs + i * TT))[tx];
            u64 b01 = pk2(xv.x, xv.y), b23 = pk2(xv.z, xv.w);
            u64 a0 = pk2(th.x, th.x), a1 = pk2(th.y, th.y);
            u64 a2 = pk2(th.z, th.z), a3 = pk2(th.w, th.w);
            fma2(acc[0][0], a0, b01); fma2(acc[0][1], a0, b23);
            fma2(acc[1][0], a1, b01); fma2(acc[1][1], a1, b23);
            fma2(acc[2][0], a2, b01); fma2(acc[2][1], a2, b23);
            fma2(acc[3][0], a3, b01); fma2(acc[3][1], a3, b23);
        }

        float* orow = g_xt + ((size_t)((b * KK_ + k) * NN + m)) * CC;
        #pragma unroll
        for (int oi = 0; oi < 4; oi++) {
            float4 v;
            unpk2(acc[oi][0], v.x, v.y);
            unpk2(acc[oi][1], v.z, v.w);
            v.x = tf32r(v.x); v.y = tf32r(v.y); v.z = tf32r(v.z); v.w = tf32r(v.w);
            *(float4*)(orow + (size_t)(ty * 4 + oi) * TT + tx * 4) = v;
        }
    }
}

// ---------------------------------------------------------------------------
// K3: mma.sync tf32 GEMM + ReLU, B read NATIVELY from g_xt [kc][c] rows.
// out[b](512x4096) = g_aeff[b](512x1536) @ g_xt[b](1536x4096)
// CTA tile M=128, N=256, BK=32; 4-stage cp.async; 512 thr = 16 warps (4Mx4N).
// A smem: [128n][32k] SW128-swizzled (16384 B).
// B smem: [32k][256n + 8 pad] rows of 1056 B (33792 B) -> bank = 8*tig+g,
//         conflict-free fragment LDS, coalesced cp.async from g_xt.
// ---------------------------------------------------------------------------
#define A_BYTES  16384
#define B_ROW    1056                       // (256+8)*4
#define B_BYTES  (32 * B_ROW)               // 33792
#define ST_BYTES (A_BYTES + B_BYTES)        // 50176
#define SMEM_GEMM (4 * ST_BYTES + 1024)

__global__ __launch_bounds__(512, 1)
void k_gemm_tc(float* __restrict__ Cg)
{
    extern __shared__ char dsm[];
    uint32_t base = (smem_u32(dsm) + 1023) & ~1023u;

    int tid  = threadIdx.x;
    int lane = tid & 31, wid = tid >> 5;
    int wm = wid & 3, wn = wid >> 2;
    int g = lane >> 2, tig = lane & 3;
    uint32_t xorv = (uint32_t)g << 4;

    int b = blockIdx.z, nt = blockIdx.y, ct = blockIdx.x;
    const float* Abase = g_aeff + ((size_t)(b * NN) + nt * 128) * KC;
    const float* Bbase = g_xt   + (size_t)b * KC * CC + ct * 256;

    const int NCHUNK = KC / 32;   // 48

    float acc[2][8][4] = {};

    // A: 1024 f4 (2/thread); B: 2048 f4 (4/thread), row-major k x n
    #define ISSUE(kt, s) do {                                                   \
        uint32_t stA = base + (s) * ST_BYTES, stB = stA + A_BYTES;              \
        int koff = (kt) * 32;                                                   \
        _Pragma("unroll")                                                       \
        for (int r = 0; r < 2; r++) {                                           \
            int idx = tid + r * 512;                                            \
            int row = idx >> 3, p = idx & 7;                                    \
            cp16(stA + SWZ((uint32_t)(row * 128 + p * 16)),                     \
                 Abase + (size_t)row * KC + koff + p * 4);                      \
        }                                                                       \
        _Pragma("unroll")                                                       \
        for (int r = 0; r < 4; r++) {                                           \
            int idx = tid + r * 512;                                            \
            int krow = idx >> 6, p = idx & 63;                                  \
            cp16(stB + (uint32_t)(krow * B_ROW + p * 16),                       \
                 Bbase + (size_t)(koff + krow) * CC + p * 4);                   \
        }                                                                       \
    } while (0)

    ISSUE(0, 0); CP_COMMIT();
    ISSUE(1, 1); CP_COMMIT();
    ISSUE(2, 2); CP_COMMIT();

    uint32_t bcol = (uint32_t)(wn * 64 + g) * 4;   // n-offset within B row

    for (int kt = 0; kt < NCHUNK; kt++) {
        CP_WAIT2();
        __syncthreads();
        int s = kt & 3;
        uint32_t stA = base + s * ST_BYTES, stB = stA + A_BYTES;

        #pragma unroll
        for (int ks = 0; ks < 4; ks++) {
            uint32_t col0 = ((uint32_t)(ks * 8 + tig) * 4) ^ xorv;
            uint32_t col1 = ((uint32_t)(ks * 8 + tig + 4) * 4) ^ xorv;
            uint32_t brow0 = stB + (uint32_t)(ks * 8 + tig) * B_ROW + bcol;
            uint32_t a[2][4], bb[8][2];
            #pragma unroll
            for (int i = 0; i < 2; i++) {
                uint32_t r0 = (uint32_t)(wm * 32 + i * 16 + g) * 128;
                a[i][0] = lds32(stA + r0 + col0);
                a[i][1] = lds32(stA + r0 + 1024 + col0);
                a[i][2] = lds32(stA + r0 + col1);
                a[i][3] = lds32(stA + r0 + 1024 + col1);
            }
            #pragma unroll
            for (int j = 0; j < 8; j++) {
                bb[j][0] = lds32(brow0 + (uint32_t)(j * 8) * 4);
                bb[j][1] = lds32(brow0 + 4 * B_ROW + (uint32_t)(j * 8) * 4);
            }
            #pragma unroll
            for (int i = 0; i < 2; i++)
                #pragma unroll
                for (int j = 0; j < 8; j++)
                    mma_tf32(acc[i][j], a[i], bb[j]);
        }

        if (kt + 3 < NCHUNK) ISSUE(kt + 3, (kt + 3) & 3);
        CP_COMMIT();
    }

    float* C = Cg + ((size_t)(b * NN) + nt * 128) * CC + ct * 256;
    #pragma unroll
    for (int i = 0; i < 2; i++) {
        int row0 = wm * 32 + i * 16 + g;
        #pragma unroll
        for (int j = 0; j < 8; j++) {
            int col = wn * 64 + j * 8 + tig * 2;
            float2 v0 = make_float2(fmaxf(acc[i][j][0], 0.f), fmaxf(acc[i][j][1], 0.f));
            float2 v1 = make_float2(fmaxf(acc[i][j][2], 0.f), fmaxf(acc[i][j][3], 0.f));
            *(float2*)(C + (size_t)row0 * CC + col) = v0;
            *(float2*)(C + (size_t)(row0 + 8) * CC + col) = v1;
        }
    }
    #undef ISSUE
}

extern "C" void kernel_launch(void* const* d_in, const int* in_sizes, int n_in,
                              void* d_out, int out_size)
{
    const float* x     = (const float*)d_in[0];
    const float* sc    = (const float*)d_in[1];
    const float* adj   = (const float*)d_in[2];
    const float* cheb  = (const float*)d_in[3];
    const float* Theta = (const float*)d_in[4];
    const float* mask  = (const float*)d_in[5];
    float* out = (float*)d_out;
    (void)in_sizes; (void)n_in; (void)out_size;

    cudaFuncSetAttribute(k_gemm_tc, cudaFuncAttributeMaxDynamicSharedMemorySize, SMEM_GEMM);

    k_aeff<<<dim3(NN, KK_, BB), 128>>>(sc, adj, mask, cheb);
    k_xtheta<<<dim3(NN, BB), 256>>>(x, Theta);
    k_gemm_tc<<<dim3(CC / 256, NN / 128, BB), 512, SMEM_GEMM>>>(out);
}

// round 11
// speedup vs baseline: 2.9655x; 1.0506x over previous
#include <cuda_runtime.h>
#include <cstdint>

#define BB   32
#define KK_  3
#define NN   512
#define FIN  64
#define FOUT 64
#define TT   64
#define KC   (KK_ * NN)          // 1536
#define CC   (FOUT * TT)         // 4096

__device__ float g_aeff[(size_t)BB * NN * KC];   // [b][n][k*512+m]  (tf32-rounded)
__device__ float g_xt  [(size_t)BB * KC * CC];   // [b][kc][c]       (tf32-rounded)

typedef unsigned long long u64;

__device__ __forceinline__ u64 pk2(float x, float y) {
    u64 r; asm("mov.b64 %0, {%1, %2};" : "=l"(r) : "f"(x), "f"(y)); return r;
}
__device__ __forceinline__ void fma2(u64 &c, u64 a, u64 b) {
    asm("fma.rn.f32x2 %0, %1, %2, %0;" : "+l"(c) : "l"(a), "l"(b));
}
__device__ __forceinline__ void unpk2(u64 v, float &x, float &y) {
    asm("mov.b64 {%0, %1}, %2;" : "=f"(x), "=f"(y) : "l"(v));
}
__device__ __forceinline__ float tf32r(float x) {
    float r; asm("cvt.rna.tf32.f32 %0, %1;" : "=f"(r) : "f"(x)); return r;
}
__device__ __forceinline__ uint32_t smem_u32(const void* p) {
    uint32_t a;
    asm("{ .reg .u64 t; cvta.to.shared.u64 t, %1; cvt.u32.u64 %0, t; }" : "=r"(a) : "l"(p));
    return a;
}
__device__ __forceinline__ void cp16(uint32_t dst, const void* src) {
    asm volatile("cp.async.cg.shared.global [%0], [%1], 16;" :: "r"(dst), "l"(src));
}
__device__ __forceinline__ uint32_t lds32(uint32_t a) {
    uint32_t v; asm("ld.shared.b32 %0, [%1];" : "=r"(v) : "r"(a)); return v;
}
__device__ __forceinline__ void mma_tf32(float* c, const uint32_t* a, const uint32_t* b) {
    asm("mma.sync.aligned.m16n8k8.row.col.f32.tf32.tf32.f32 "
        "{%0,%1,%2,%3}, {%4,%5,%6,%7}, {%8,%9}, {%0,%1,%2,%3};"
        : "+f"(c[0]), "+f"(c[1]), "+f"(c[2]), "+f"(c[3])
        : "r"(a[0]), "r"(a[1]), "r"(a[2]), "r"(a[3]), "r"(b[0]), "r"(b[1]));
}
#define CP_COMMIT() asm volatile("cp.async.commit_group;" ::: "memory")
#define CP_WAIT2()  asm volatile("cp.async.wait_group 2;" ::: "memory")
#define SWZ(bo) ((bo) ^ (((bo) >> 3) & 0x70))

// ---------------------------------------------------------------------------
// K1: softmax + A_eff, written [b][n][k*512+m], tf32-rounded
// ---------------------------------------------------------------------------
__global__ __launch_bounds__(128)
void k_aeff(const float* __restrict__ sc, const float* __restrict__ adj,
            const float* __restrict__ mask, const float* __restrict__ cheb)
{
    int n = blockIdx.x, k = blockIdx.y, b = blockIdx.z;
    const float4* s4 = (const float4*)(sc   + (((size_t)(b * KK_ + k)) * NN + n) * NN);
    const float4* a4 = (const float4*)(adj  + (size_t)n * NN);
    const float4* m4 = (const float4*)(mask + ((size_t)(k * NN + n)) * NN);
    const float4* c4 = (const float4*)(cheb + ((size_t)(k * NN + n)) * NN);
    float4*       o4 = (float4*)(g_aeff + ((size_t)(b * NN + n)) * KC + k * NN);

    int t = threadIdx.x;
    float4 sv = s4[t], av = a4[t], mv = m4[t];
    float v0 = sv.x + av.x * mv.x;
    float v1 = sv.y + av.y * mv.y;
    float v2 = sv.z + av.z * mv.z;
    float v3 = sv.w + av.w * mv.w;

    float mx = fmaxf(fmaxf(v0, v1), fmaxf(v2, v3));
    __shared__ float red[4];
    #pragma unroll
    for (int o = 16; o; o >>= 1) mx = fmaxf(mx, __shfl_xor_sync(0xffffffffu, mx, o));
    if ((t & 31) == 0) red[t >> 5] = mx;
    __syncthreads();
    mx = fmaxf(fmaxf(red[0], red[1]), fmaxf(red[2], red[3]));
    __syncthreads();

    v0 = __expf(v0 - mx); v1 = __expf(v1 - mx);
    v2 = __expf(v2 - mx); v3 = __expf(v3 - mx);
    float s = v0 + v1 + v2 + v3;
    #pragma unroll
    for (int o = 16; o; o >>= 1) s += __shfl_xor_sync(0xffffffffu, s, o);
    if ((t & 31) == 0) red[t >> 5] = s;
    __syncthreads();
    s = red[0] + red[1] + red[2] + red[3];
    float inv = 1.0f / s;

    float4 cv = c4[t];
    float4 ov;
    ov.x = tf32r(cv.x * v0 * inv); ov.y = tf32r(cv.y * v1 * inv);
    ov.z = tf32r(cv.z * v2 * inv); ov.w = tf32r(cv.w * v3 * inv);
    o4[t] = ov;
}

// ---------------------------------------------------------------------------
// K2: XT[b,k,m,c] = sum_i x[b,m,i,t] * Theta[k,i,o], tf32-rounded
// ---------------------------------------------------------------------------
__global__ __launch_bounds__(256)
void k_xtheta(const float* __restrict__ x, const float* __restrict__ Theta)
{
    int m = blockIdx.x, b = blockIdx.y;
    __shared__ float Xs[FIN * TT];
    __shared__ float Ts[FIN * FOUT];

    int tid = threadIdx.x;
    const float4* xb4 = (const float4*)(x + ((size_t)(b * NN + m)) * (FIN * TT));
    float4* Xs4 = (float4*)Xs;
    #pragma unroll
    for (int r = 0; r < 4; r++) Xs4[tid + r * 256] = xb4[tid + r * 256];

    int tx = tid & 15;
    int ty = tid >> 4;

    for (int k = 0; k < KK_; k++) {
        __syncthreads();
        const float4* th4 = (const float4*)(Theta + (size_t)k * FIN * FOUT);
        float4* Ts4 = (float4*)Ts;
        #pragma unroll
        for (int r = 0; r < 4; r++) Ts4[tid + r * 256] = th4[tid + r * 256];
        __syncthreads();

        u64 acc[4][2] = {};
        #pragma unroll 8
        for (int i = 0; i < FIN; i++) {
            float4 th = ((const float4*)(Ts + i * FOUT))[ty];
            float4 xv = ((const float4*)(Xs + i * TT))[tx];
            u64 b01 = pk2(xv.x, xv.y), b23 = pk2(xv.z, xv.w);
            u64 a0 = pk2(th.x, th.x), a1 = pk2(th.y, th.y);
            u64 a2 = pk2(th.z, th.z), a3 = pk2(th.w, th.w);
            fma2(acc[0][0], a0, b01); fma2(acc[0][1], a0, b23);
            fma2(acc[1][0], a1, b01); fma2(acc[1][1], a1, b23);
            fma2(acc[2][0], a2, b01); fma2(acc[2][1], a2, b23);
            fma2(acc[3][0], a3, b01); fma2(acc[3][1], a3, b23);
        }

        float* orow = g_xt + ((size_t)((b * KK_ + k) * NN + m)) * CC;
        #pragma unroll
        for (int oi = 0; oi < 4; oi++) {
            float4 v;
            unpk2(acc[oi][0], v.x, v.y);
            unpk2(acc[oi][1], v.z, v.w);
            v.x = tf32r(v.x); v.y = tf32r(v.y); v.z = tf32r(v.z); v.w = tf32r(v.w);
            *(float4*)(orow + (size_t)(ty * 4 + oi) * TT + tx * 4) = v;
        }
    }
}

// ---------------------------------------------------------------------------
// K3: mma.sync tf32 GEMM + ReLU. CTA tile M=128, N=256, BK=32; 4-stage
// cp.async; 256 thr = 8 warps as 2(M) x 4(N), warp tile 64x64
// (4 m16 x 8 n8 = 32 MMAs/ks). Smem reads/chunk: A 16K*4 + B 33K*2 = 130KB
// (~1024 crossbar cyc) vs 1024 MMA cyc -> balanced.
// A smem: [128][32] SW128-swizzled. B smem: [32][256+8pad] rows (1056 B).
// ---------------------------------------------------------------------------
#define A_BYTES  16384
#define B_ROW    1056
#define B_BYTES  (32 * B_ROW)
#define ST_BYTES (A_BYTES + B_BYTES)        // 50176
#define SMEM_GEMM (4 * ST_BYTES + 1024)

__global__ __launch_bounds__(256, 1)
void k_gemm_tc(float* __restrict__ Cg)
{
    extern __shared__ char dsm[];
    uint32_t base = (smem_u32(dsm) + 1023) & ~1023u;

    int tid  = threadIdx.x;
    int lane = tid & 31, wid = tid >> 5;
    int wm = wid & 1, wn = wid >> 1;        // 2 M-groups x 4 N-groups
    int g = lane >> 2, tig = lane & 3;
    uint32_t xorv = (uint32_t)g << 4;

    int b = blockIdx.z, nt = blockIdx.y, ct = blockIdx.x;
    const float* Abase = g_aeff + ((size_t)(b * NN) + nt * 128) * KC;
    const float* Bbase = g_xt   + (size_t)b * KC * CC + ct * 256;

    const int NCHUNK = KC / 32;   // 48

    float acc[4][8][4] = {};

    // A: 1024 f4 (4/thread); B: 2048 f4 (8/thread)
    #define ISSUE(kt, s) do {                                                   \
        uint32_t stA = base + (s) * ST_BYTES, stB = stA + A_BYTES;              \
        int koff = (kt) * 32;                                                   \
        _Pragma("unroll")                                                       \
        for (int r = 0; r < 4; r++) {                                           \
            int idx = tid + r * 256;                                            \
            int row = idx >> 3, p = idx & 7;                                    \
            cp16(stA + SWZ((uint32_t)(row * 128 + p * 16)),                     \
                 Abase + (size_t)row * KC + koff + p * 4);                      \
        }                                                                       \
        _Pragma("unroll")                                                       \
        for (int r = 0; r < 8; r++) {                                           \
            int idx = tid + r * 256;                                            \
            int krow = idx >> 6, p = idx & 63;                                  \
            cp16(stB + (uint32_t)(krow * B_ROW + p * 16),                       \
                 Bbase + (size_t)(koff + krow) * CC + p * 4);                   \
        }                                                                       \
    } while (0)

    ISSUE(0, 0); CP_COMMIT();
    ISSUE(1, 1); CP_COMMIT();
    ISSUE(2, 2); CP_COMMIT();

    uint32_t bcol = (uint32_t)(wn * 64 + g) * 4;   // n-offset within B row

    for (int kt = 0; kt < NCHUNK; kt++) {
        CP_WAIT2();
        __syncthreads();
        int s = kt & 3;
        uint32_t stA = base + s * ST_BYTES, stB = stA + A_BYTES;

        #pragma unroll
        for (int ks = 0; ks < 4; ks++) {
            uint32_t col0 = ((uint32_t)(ks * 8 + tig) * 4) ^ xorv;
            uint32_t col1 = ((uint32_t)(ks * 8 + tig + 4) * 4) ^ xorv;
            uint32_t brow0 = stB + (uint32_t)(ks * 8 + tig) * B_ROW + bcol;
            uint32_t a[4][4], bb[8][2];
            #pragma unroll
            for (int i = 0; i < 4; i++) {
                uint32_t r0 = (uint32_t)(wm * 64 + i * 16 + g) * 128;
                a[i][0] = lds32(stA + r0 + col0);
                a[i][1] = lds32(stA + r0 + 1024 + col0);   // +8 rows
                a[i][2] = lds32(stA + r0 + col1);
                a[i][3] = lds32(stA + r0 + 1024 + col1);
            }
            #pragma unroll
            for (int j = 0; j < 8; j++) {
                bb[j][0] = lds32(brow0 + (uint32_t)(j * 8) * 4);
                bb[j][1] = lds32(brow0 + 4 * B_ROW + (uint32_t)(j * 8) * 4);
            }
            #pragma unroll
            for (int i = 0; i < 4; i++)
                #pragma unroll
                for (int j = 0; j < 8; j++)
                    mma_tf32(acc[i][j], a[i], bb[j]);
        }

        if (kt + 3 < NCHUNK) ISSUE(kt + 3, (kt + 3) & 3);
        CP_COMMIT();
    }

    float* C = Cg + ((size_t)(b * NN) + nt * 128) * CC + ct * 256;
    #pragma unroll
    for (int i = 0; i < 4; i++) {
        int row0 = wm * 64 + i * 16 + g;
        #pragma unroll
        for (int j = 0; j < 8; j++) {
            int col = wn * 64 + j * 8 + tig * 2;
            float2 v0 = make_float2(fmaxf(acc[i][j][0], 0.f), fmaxf(acc[i][j][1], 0.f));
            float2 v1 = make_float2(fmaxf(acc[i][j][2], 0.f), fmaxf(acc[i][j][3], 0.f));
            *(float2*)(C + (size_t)row0 * CC + col) = v0;
            *(float2*)(C + (size_t)(row0 + 8) * CC + col) = v1;
        }
    }
    #undef ISSUE
}

extern "C" void kernel_launch(void* const* d_in, const int* in_sizes, int n_in,
                              void* d_out, int out_size)
{
    const float* x     = (const float*)d_in[0];
    const float* sc    = (const float*)d_in[1];
    const float* adj   = (const float*)d_in[2];
    const float* cheb  = (const float*)d_in[3];
    const float* Theta = (const float*)d_in[4];
    const float* mask  = (const float*)d_in[5];
    float* out = (float*)d_out;
    (void)in_sizes; (void)n_in; (void)out_size;

    cudaFuncSetAttribute(k_gemm_tc, cudaFuncAttributeMaxDynamicSharedMemorySize, SMEM_GEMM);

    k_aeff<<<dim3(NN, KK_, BB), 128>>>(sc, adj, mask, cheb);
    k_xtheta<<<dim3(NN, BB), 256>>>(x, Theta);
    k_gemm_tc<<<dim3(CC / 256, NN / 128, BB), 256, SMEM_GEMM>>>(out);
}